// round 7
// baseline (speedup 1.0000x reference)
#include <cuda_runtime.h>
#include <cuda_fp16.h>
#include <math.h>

#define H 192
#define W 192
#define HW (H*W)
#define NCH 24          // BT*C = 8*3
#define CROP 174
#define H0 9
#define W0 9
#define NPIX (CROP*CROP)        // 30276
#define NCAND 75
#define SPLIT 15        // 75*15 = 1125 blocks < 148*8 = 1184 -> single wave
#define NBT 8
#define NLANES 64       // pixel lanes per block
#define NTHR 192        // NLANES * 3 groups
#define IMG_BLKS (HW / 256)                 // 144
#define REF_BLKS ((NPIX + 255) / 256)       // 119

__device__ __half g_imgT[HW * NCH];           // [y][x][ch] fp16
__device__ __half g_refT[NPIX * NCH];         // [i][j][ch] fp16
__device__ float  g_partial[NCAND * SPLIT * NBT];
__device__ int    g_count;

// ---------------------------------------------------------------------------
// Convert+transpose via smem tiles: coalesced channel-row reads, coalesced
// 4B record writes. Blocks [0,144) do the image, [144,263) the ref crop.
// Also resets the completion counter used by the fused finalize.
// ---------------------------------------------------------------------------
__global__ __launch_bounds__(256) void convert_kernel(const float* __restrict__ img,
                                                      const float* __restrict__ ref) {
    __shared__ __half s[256][26];   // stride 26 halves = 52 B (4-aligned)
    const int b = blockIdx.x;
    const int tid = threadIdx.x;
    if (b == 0 && tid == 0) g_count = 0;

    if (b < IMG_BLKS) {
        const int p0 = b * 256;
        #pragma unroll
        for (int ch = 0; ch < NCH; ch++)
            s[tid][ch] = __float2half(img[ch * HW + p0 + tid]);
        __syncthreads();
        unsigned int* out32 = (unsigned int*)g_imgT;
        #pragma unroll
        for (int w = 0; w < 12; w++) {
            const int idx = w * 256 + tid;       // 0..3071
            const int px = idx / 12;
            const int u  = idx - px * 12;
            out32[p0 * 12 + idx] = *(const unsigned int*)&s[px][2 * u];
        }
    } else {
        const int p0 = (b - IMG_BLKS) * 256;
        const int p = p0 + tid;
        const bool valid = (p < NPIX);
        const int i = p / CROP;
        const int j = p - i * CROP;
        const int src = (i + H0) * W + (j + W0);
        #pragma unroll
        for (int ch = 0; ch < NCH; ch++)
            s[tid][ch] = valid ? __float2half(ref[ch * HW + src]) : __half(0.0f);
        __syncthreads();
        const int total32 = (min(256, NPIX - p0)) * 12;
        unsigned int* out32 = (unsigned int*)g_refT;
        #pragma unroll
        for (int w = 0; w < 12; w++) {
            const int idx = w * 256 + tid;
            if (idx < total32) {
                const int px = idx / 12;
                const int u  = idx - px * 12;
                out32[p0 * 12 + idx] = *(const unsigned int*)&s[px][2 * u];
            }
        }
    }
}

// ---------------------------------------------------------------------------
// Main SAD kernel (fp16 data, half2 math) + fused finalize (last block).
// Block = 192 threads = 64 pixel-lanes x 3 channel-groups (8 ch each).
// Grid  = (NCAND, SPLIT) = 1125 blocks -> single wave at 8 blocks/SM.
// |d| accumulated in half2 over 4-iter chunks, flushed to fp32 -> saves
// 12 instr/iter vs per-iter fp32 accumulation.
// ---------------------------------------------------------------------------
__global__ __launch_bounds__(NTHR, 8) void sad_kernel(float* __restrict__ out,
                                                      int out_size) {
    const int n = blockIdx.x;
    const int s = blockIdx.y;
    const int t = threadIdx.x;
    const int g = t % 3;          // channel group: ch = 8g .. 8g+7
    const int lane_px = t / 3;    // 0..63
    const int g8 = 8 * g;

    // Candidate parameters: n = i0*15 + i1*3 + i2  (DIMS 5,5,3,1)
    const int i0 = n / 15;
    const int i1 = (n / 3) % 5;
    const int i2 = n % 3;
    const float ash = (float)(2 - i0);
    const float asw = (float)(2 - i1);
    const float arot = -(float)(i2 - 1) * (float)(M_PI / 180.0);
    const float cr = cosf(arot);
    const float sr = sinf(arot);

    // Affine map: x = ax*j + bx*i + cx0 ; y = ay*j + by*i + cy0
    const float SC = 96.0f / 95.5f;
    const float u0 = asw - 86.5f;
    const float v0 = ash - 86.5f;
    const float ax = SC * cr;
    const float bx = -SC * sr;
    const float cx0 = SC * (cr * u0 - sr * v0) + 95.5f;
    const float ay = SC * sr;
    const float by = SC * cr;
    const float cy0 = SC * (sr * u0 + cr * v0) + 95.5f;

    float acc[8];
    #pragma unroll
    for (int k = 0; k < 8; k++) acc[k] = 0.0f;

    const int chunk = (NPIX + SPLIT - 1) / SPLIT;
    const int p_begin = s * chunk;
    const int p_end   = min(p_begin + chunk, NPIX);

    // Incremental (i, j): stride 64 < CROP so at most one row wrap per step.
    int pi, pj;
    {
        const int p0 = p_begin + lane_px;
        pi = p0 / CROP;
        pj = p0 - pi * CROP;
    }

    const __half2 hz = __float2half2_rn(0.0f);

    for (int pp = p_begin + lane_px; pp < p_end; pp += 4 * NLANES) {
        __half2 a2_0 = hz, a2_1 = hz, a2_2 = hz, a2_3 = hz;

        #pragma unroll
        for (int q = 0; q < 4; q++) {
            const int p = pp + q * NLANES;
            if (p < p_end) {
                const float x = fmaf(ax, (float)pj, fmaf(bx, (float)pi, cx0));
                const float y = fmaf(ay, (float)pj, fmaf(by, (float)pi, cy0));

                const float x0f = floorf(x);
                const float y0f = floorf(y);
                const float wx = x - x0f;
                const float wy = y - y0f;
                const int x0 = (int)x0f;
                const int y0 = (int)y0f;

                const float wx1 = 1.0f - wx;
                const float wy1 = 1.0f - wy;
                const __half2 wA2 = __float2half2_rn(wx1 * wy1);
                const __half2 wB2 = __float2half2_rn(wx  * wy1);
                const __half2 wC2 = __float2half2_rn(wx1 * wy);
                const __half2 wD2 = __float2half2_rn(wx  * wy);

                const int base = (y0 * W + x0) * NCH + g8;

                const float4 fA = *(const float4*)(g_imgT + base);
                const float4 fB = *(const float4*)(g_imgT + base + NCH);
                const float4 fC = *(const float4*)(g_imgT + base + W * NCH);
                const float4 fD = *(const float4*)(g_imgT + base + W * NCH + NCH);
                const float4 fR = *(const float4*)(g_refT + p * NCH + g8);

                const __half2* hA = (const __half2*)&fA;
                const __half2* hB = (const __half2*)&fB;
                const __half2* hC = (const __half2*)&fC;
                const __half2* hD = (const __half2*)&fD;
                const __half2* hR = (const __half2*)&fR;

                {
                    __half2 tv = __hmul2(wA2, hA[0]);
                    tv = __hfma2(wB2, hB[0], tv);
                    tv = __hfma2(wC2, hC[0], tv);
                    tv = __hfma2(wD2, hD[0], tv);
                    a2_0 = __hadd2(a2_0, __habs2(__hsub2(tv, hR[0])));
                }
                {
                    __half2 tv = __hmul2(wA2, hA[1]);
                    tv = __hfma2(wB2, hB[1], tv);
                    tv = __hfma2(wC2, hC[1], tv);
                    tv = __hfma2(wD2, hD[1], tv);
                    a2_1 = __hadd2(a2_1, __habs2(__hsub2(tv, hR[1])));
                }
                {
                    __half2 tv = __hmul2(wA2, hA[2]);
                    tv = __hfma2(wB2, hB[2], tv);
                    tv = __hfma2(wC2, hC[2], tv);
                    tv = __hfma2(wD2, hD[2], tv);
                    a2_2 = __hadd2(a2_2, __habs2(__hsub2(tv, hR[2])));
                }
                {
                    __half2 tv = __hmul2(wA2, hA[3]);
                    tv = __hfma2(wB2, hB[3], tv);
                    tv = __hfma2(wC2, hC[3], tv);
                    tv = __hfma2(wD2, hD[3], tv);
                    a2_3 = __hadd2(a2_3, __habs2(__hsub2(tv, hR[3])));
                }
            }
            pj += NLANES;
            if (pj >= CROP) { pj -= CROP; pi += 1; }
        }

        // Flush half2 partials into fp32 accumulators (deterministic order).
        {
            const float2 d0 = __half22float2(a2_0);
            const float2 d1 = __half22float2(a2_1);
            const float2 d2 = __half22float2(a2_2);
            const float2 d3 = __half22float2(a2_3);
            acc[0] += d0.x; acc[1] += d0.y;
            acc[2] += d1.x; acc[3] += d1.y;
            acc[4] += d2.x; acc[5] += d2.y;
            acc[6] += d3.x; acc[7] += d3.y;
        }
    }

    // ---- Deterministic block reduction ----
    __shared__ float sc[8 * NTHR];
    __shared__ float s2[NBT * 24];
    #pragma unroll
    for (int k = 0; k < 8; k++) sc[k * NTHR + t] = acc[k];
    __syncthreads();
    {
        const int bt = t / 24;
        const int ii = t % 24;
        const int c  = bt * 3 + ii / 8;
        const int gs = c / 8;
        const int k  = c % 8;
        const int m8 = ii % 8;
        float ssum = 0.0f;
        #pragma unroll
        for (int jj = 0; jj < 8; jj++)
            ssum += sc[k * NTHR + gs + 3 * (m8 * 8 + jj)];
        s2[bt * 24 + ii] = ssum;
    }
    __syncthreads();
    if (t < NBT) {
        float ssum = 0.0f;
        #pragma unroll
        for (int ii = 0; ii < 24; ii++)
            ssum += s2[t * 24 + ii];
        g_partial[(n * SPLIT + s) * NBT + t] = ssum;
    }

    // ---- Fused finalize: last block to finish does the reduction ----
    __shared__ int isLast;
    __threadfence();
    __syncthreads();
    if (t == 0) {
        const int old = atomicAdd(&g_count, 1);
        isLast = (old == NCAND * SPLIT - 1) ? 1 : 0;
    }
    __syncthreads();
    if (isLast) {
        __shared__ float sadSh[NCAND * NBT];
        for (int idx = t; idx < NCAND * NBT; idx += NTHR) {
            const int nn = idx / NBT;
            const int bt = idx - nn * NBT;
            float ssum = 0.0f;
            #pragma unroll
            for (int k = 0; k < SPLIT; k++)
                ssum += __ldcg(&g_partial[(nn * SPLIT + k) * NBT + bt]);
            ssum *= (1.0f / (float)(3 * NPIX));
            sadSh[idx] = ssum;
            out[idx] = ssum;
        }
        __syncthreads();
        if (t < NBT && out_size >= NCAND * NBT + 4 * NBT) {
            const int bt = t;
            float best = sadSh[bt];
            int bn = 0;
            for (int nn = 1; nn < NCAND; nn++) {
                const float v = sadSh[nn * NBT + bt];
                if (v < best) { best = v; bn = nn; }
            }
            const int a0 = bn / 15;
            const int a1 = (bn / 3) % 5;
            const int a2 = bn % 3;
            out[NCAND * NBT + 0 * NBT + bt] = (float)a0;
            out[NCAND * NBT + 1 * NBT + bt] = (float)a1;
            out[NCAND * NBT + 2 * NBT + bt] = (float)a2;
            out[NCAND * NBT + 3 * NBT + bt] = 0.0f;
        }
    }
}

extern "C" void kernel_launch(void* const* d_in, const int* in_sizes, int n_in,
                              void* d_out, int out_size) {
    const float* matrix = (const float*)d_in[0];
    const float* refm   = (const float*)d_in[1];

    convert_kernel<<<IMG_BLKS + REF_BLKS, 256>>>(matrix, refm);

    dim3 grid(NCAND, SPLIT);
    sad_kernel<<<grid, NTHR>>>((float*)d_out, out_size);
}

// round 8
// speedup vs baseline: 1.2639x; 1.2639x over previous
#include <cuda_runtime.h>
#include <cuda_fp16.h>
#include <math.h>

#define H 192
#define W 192
#define HW (H*W)
#define NCH 24          // BT*C = 8*3
#define CROP 174
#define H0 9
#define W0 9
#define NPIX (CROP*CROP)        // 30276
#define NCAND 75
#define SPLIT 15        // 75*15 = 1125 blocks < 148*8 = 1184 -> single wave
#define NBT 8
#define NLANES 64       // pixel lanes per block
#define NTHR 192        // NLANES * 3 groups
#define IMG_BLKS (HW / 256)                 // 144
#define REF_BLKS ((NPIX + 255) / 256)       // 119

__device__ __half g_imgT[HW * NCH];           // [y][x][ch] fp16
__device__ __half g_refT[NPIX * NCH];         // [i][j][ch] fp16
__device__ float  g_partial[NCAND * SPLIT * NBT];
__device__ int    g_count;

// ---------------------------------------------------------------------------
// Convert+transpose via smem tiles: coalesced channel-row reads, coalesced
// 4B record writes. Blocks [0,144) do the image, [144,263) the ref crop.
// Also resets the completion counter used by the fused finalize.
// ---------------------------------------------------------------------------
__global__ __launch_bounds__(256) void convert_kernel(const float* __restrict__ img,
                                                      const float* __restrict__ ref) {
    __shared__ __half s[256][26];   // stride 26 halves = 52 B (4-aligned)
    const int b = blockIdx.x;
    const int tid = threadIdx.x;
    if (b == 0 && tid == 0) g_count = 0;

    if (b < IMG_BLKS) {
        const int p0 = b * 256;
        #pragma unroll
        for (int ch = 0; ch < NCH; ch++)
            s[tid][ch] = __float2half(img[ch * HW + p0 + tid]);
        __syncthreads();
        unsigned int* out32 = (unsigned int*)g_imgT;
        #pragma unroll
        for (int w = 0; w < 12; w++) {
            const int idx = w * 256 + tid;       // 0..3071
            const int px = idx / 12;
            const int u  = idx - px * 12;
            out32[p0 * 12 + idx] = *(const unsigned int*)&s[px][2 * u];
        }
    } else {
        const int p0 = (b - IMG_BLKS) * 256;
        const int p = p0 + tid;
        const bool valid = (p < NPIX);
        const int i = p / CROP;
        const int j = p - i * CROP;
        const int src = (i + H0) * W + (j + W0);
        #pragma unroll
        for (int ch = 0; ch < NCH; ch++)
            s[tid][ch] = valid ? __float2half(ref[ch * HW + src]) : __half(0.0f);
        __syncthreads();
        const int total32 = (min(256, NPIX - p0)) * 12;
        unsigned int* out32 = (unsigned int*)g_refT;
        #pragma unroll
        for (int w = 0; w < 12; w++) {
            const int idx = w * 256 + tid;
            if (idx < total32) {
                const int px = idx / 12;
                const int u  = idx - px * 12;
                out32[p0 * 12 + idx] = *(const unsigned int*)&s[px][2 * u];
            }
        }
    }
}

// ---------------------------------------------------------------------------
// Main SAD kernel (fp16 data, half2 math) + fused finalize (last block).
// Block = 192 threads = 64 pixel-lanes x 3 channel-groups (8 ch each).
// Grid  = (NCAND, SPLIT) = 1125 blocks -> single wave at 8 blocks/SM.
// Coordinates advance incrementally by constant deltas (wrap-corrected);
// simple runtime-bound loop + pragma unroll 4 so the compiler emits a
// guard-free unrolled main loop with batched loads.
// ---------------------------------------------------------------------------
__global__ __launch_bounds__(NTHR, 8) void sad_kernel(float* __restrict__ out,
                                                      int out_size) {
    const int n = blockIdx.x;
    const int s = blockIdx.y;
    const int t = threadIdx.x;
    const int g = t % 3;          // channel group: ch = 8g .. 8g+7
    const int lane_px = t / 3;    // 0..63
    const int g8 = 8 * g;

    // Candidate parameters: n = i0*15 + i1*3 + i2  (DIMS 5,5,3,1)
    const int i0 = n / 15;
    const int i1 = (n / 3) % 5;
    const int i2 = n % 3;
    const float ash = (float)(2 - i0);
    const float asw = (float)(2 - i1);
    const float arot = -(float)(i2 - 1) * (float)(M_PI / 180.0);
    const float cr = cosf(arot);
    const float sr = sinf(arot);

    // Affine map: x = ax*j + bx*i + cx0 ; y = ay*j + by*i + cy0
    const float SC = 96.0f / 95.5f;
    const float u0 = asw - 86.5f;
    const float v0 = ash - 86.5f;
    const float ax = SC * cr;
    const float bx = -SC * sr;
    const float cx0 = SC * (cr * u0 - sr * v0) + 95.5f;
    const float ay = SC * sr;
    const float by = SC * cr;
    const float cy0 = SC * (sr * u0 + cr * v0) + 95.5f;

    float acc[8];
    #pragma unroll
    for (int k = 0; k < 8; k++) acc[k] = 0.0f;

    const int chunk = (NPIX + SPLIT - 1) / SPLIT;
    const int p_begin = s * chunk;
    const int p_end   = min(p_begin + chunk, NPIX);

    // Incremental state: coordinates advance by constant deltas; one row
    // wrap at most per step (stride 64 < CROP).
    int p = p_begin + lane_px;
    int pj;
    float xv, yv;
    {
        const int pi0 = p / CROP;
        pj = p - pi0 * CROP;
        xv = fmaf(ax, (float)pj, fmaf(bx, (float)pi0, cx0));
        yv = fmaf(ay, (float)pj, fmaf(by, (float)pi0, cy0));
    }
    const float dxn = ax * (float)NLANES;
    const float dxw = ax * (float)(NLANES - CROP) + bx;
    const float dyn = ay * (float)NLANES;
    const float dyw = ay * (float)(NLANES - CROP) + by;
    int refoff = p * NCH + g8;

    #pragma unroll 4
    for (; p < p_end; p += NLANES) {
        const float x = xv;
        const float y = yv;

        const float x0f = floorf(x);
        const float y0f = floorf(y);
        const float wx = x - x0f;
        const float wy = y - y0f;
        const int x0 = (int)x0f;
        const int y0 = (int)y0f;

        const float wx1 = 1.0f - wx;
        const float wy1 = 1.0f - wy;
        const __half2 wA2 = __float2half2_rn(wx1 * wy1);
        const __half2 wB2 = __float2half2_rn(wx  * wy1);
        const __half2 wC2 = __float2half2_rn(wx1 * wy);
        const __half2 wD2 = __float2half2_rn(wx  * wy);

        const int base = (y0 * W + x0) * NCH + g8;

        const float4 fA = *(const float4*)(g_imgT + base);
        const float4 fB = *(const float4*)(g_imgT + base + NCH);
        const float4 fC = *(const float4*)(g_imgT + base + W * NCH);
        const float4 fD = *(const float4*)(g_imgT + base + W * NCH + NCH);
        const float4 fR = *(const float4*)(g_refT + refoff);

        const __half2* hA = (const __half2*)&fA;
        const __half2* hB = (const __half2*)&fB;
        const __half2* hC = (const __half2*)&fC;
        const __half2* hD = (const __half2*)&fD;
        const __half2* hR = (const __half2*)&fR;

        #pragma unroll
        for (int u = 0; u < 4; u++) {
            __half2 tv = __hmul2(wA2, hA[u]);
            tv = __hfma2(wB2, hB[u], tv);
            tv = __hfma2(wC2, hC[u], tv);
            tv = __hfma2(wD2, hD[u], tv);
            const __half2 d = __habs2(__hsub2(tv, hR[u]));
            const float2 df = __half22float2(d);
            acc[2 * u]     += df.x;
            acc[2 * u + 1] += df.y;
        }

        pj += NLANES;
        const bool wrap = (pj >= CROP);
        pj = wrap ? pj - CROP : pj;
        xv += wrap ? dxw : dxn;
        yv += wrap ? dyw : dyn;
        refoff += NLANES * NCH;
    }

    // ---- Deterministic block reduction ----
    __shared__ float sc[8 * NTHR];
    __shared__ float s2[NBT * 24];
    #pragma unroll
    for (int k = 0; k < 8; k++) sc[k * NTHR + t] = acc[k];
    __syncthreads();
    {
        const int bt = t / 24;
        const int ii = t % 24;
        const int c  = bt * 3 + ii / 8;
        const int gs = c / 8;
        const int k  = c % 8;
        const int m8 = ii % 8;
        float ssum = 0.0f;
        #pragma unroll
        for (int jj = 0; jj < 8; jj++)
            ssum += sc[k * NTHR + gs + 3 * (m8 * 8 + jj)];
        s2[bt * 24 + ii] = ssum;
    }
    __syncthreads();
    if (t < NBT) {
        float ssum = 0.0f;
        #pragma unroll
        for (int ii = 0; ii < 24; ii++)
            ssum += s2[t * 24 + ii];
        g_partial[(n * SPLIT + s) * NBT + t] = ssum;
    }

    // ---- Fused finalize: last block to finish does the reduction ----
    __shared__ int isLast;
    __threadfence();
    __syncthreads();
    if (t == 0) {
        const int old = atomicAdd(&g_count, 1);
        isLast = (old == NCAND * SPLIT - 1) ? 1 : 0;
    }
    __syncthreads();
    if (isLast) {
        __shared__ float sadSh[NCAND * NBT];
        for (int idx = t; idx < NCAND * NBT; idx += NTHR) {
            const int nn = idx / NBT;
            const int bt = idx - nn * NBT;
            float ssum = 0.0f;
            #pragma unroll
            for (int k = 0; k < SPLIT; k++)
                ssum += __ldcg(&g_partial[(nn * SPLIT + k) * NBT + bt]);
            ssum *= (1.0f / (float)(3 * NPIX));
            sadSh[idx] = ssum;
            out[idx] = ssum;
        }
        __syncthreads();
        if (t < NBT && out_size >= NCAND * NBT + 4 * NBT) {
            const int bt = t;
            float best = sadSh[bt];
            int bn = 0;
            for (int nn = 1; nn < NCAND; nn++) {
                const float v = sadSh[nn * NBT + bt];
                if (v < best) { best = v; bn = nn; }
            }
            const int a0 = bn / 15;
            const int a1 = (bn / 3) % 5;
            const int a2 = bn % 3;
            out[NCAND * NBT + 0 * NBT + bt] = (float)a0;
            out[NCAND * NBT + 1 * NBT + bt] = (float)a1;
            out[NCAND * NBT + 2 * NBT + bt] = (float)a2;
            out[NCAND * NBT + 3 * NBT + bt] = 0.0f;
        }
    }
}

extern "C" void kernel_launch(void* const* d_in, const int* in_sizes, int n_in,
                              void* d_out, int out_size) {
    const float* matrix = (const float*)d_in[0];
    const float* refm   = (const float*)d_in[1];

    convert_kernel<<<IMG_BLKS + REF_BLKS, 256>>>(matrix, refm);

    dim3 grid(NCAND, SPLIT);
    sad_kernel<<<grid, NTHR>>>((float*)d_out, out_size);
}